// round 6
// baseline (speedup 1.0000x reference)
#include <cuda_runtime.h>
#include <math.h>

// ---------------------------------------------------------------------------
// BalancedFrequencyAttention, collapsed form (see R2 derivation):
//   gap[b,c] = sum_{h,n} x[b,c,h,n] * w(h,n)
//   w(h,n)   = c0 + [h>=80] * (0.4/48000) * g_{(h-80)%3}(n),  period-12 in n
//   att      = sigmoid(gap @ w1^T @ w2^T);  out = x * att[:,:,None,None]
//
// R6: reduce keeps the R4 constant-register-weight partition (5 blocks/ch:
//   2 low contiguous, 3 high with fixed (h-80)%3 class). MLP is fused into
//   the last-arriving reduce block (threadfence-reduction election, counter
//   self-resets for graph replay). Scale reverted to the R4-proven
//   1-float4/thread streaming form.
// ---------------------------------------------------------------------------

#define N_CH        1024      // B*C
#define Q_PER_CH    24000     // 200*480/4 float4 per channel
#define BLKS_PER_CH 5
#define N_BLOCKS    (N_CH * BLKS_PER_CH)

__device__ float d_part[N_CH * BLKS_PER_CH];
__device__ float d_att[N_CH];
__device__ unsigned int d_count = 0;

// ---- Kernel 1: weighted reduction + fused MLP in the last block --------------
__global__ __launch_bounds__(256, 8) void reduce_kernel(const float4* __restrict__ x,
                                                        const float* __restrict__ w1,
                                                        const float* __restrict__ w2) {
    const float c0  = 8.838834764831843e-06f;   // 0.6/sqrt(2)/48000
    const float inv = 8.333333333333334e-06f;   // 0.4/48000
    const float PI  = 3.14159265358979323846f;

    const int blk = blockIdx.x;
    const int ch  = blk / BLKS_PER_CH;
    const int s   = blk - ch * BLKS_PER_CH;

    const int t    = threadIdx.x;
    const int c4   = t & 127;          // float4 column (0..119 active)
    const int r    = t >> 7;           // row-within-pair (0/1)
    const bool act = (c4 < 120);

    // Per-thread constant weight (computed once).
    float4 w = make_float4(c0, c0, c0, c0);
    if (s >= 2) {
        const int k  = s - 2;
        const int n0 = c4 << 2;
        float g[4];
        #pragma unroll
        for (int e = 0; e < 4; e++) {
            float a = (float)(2 * ((n0 + e) % 12) + 1);
            float gv;
            if (k == 0)      gv = cosf(a * (PI / 12.f)) + cosf(a * (PI / 3.f));
            else if (k == 1) gv = cosf(a * (PI / 6.f))  + cosf(a * (5.f * PI / 12.f));
            else             gv = cosf(a * (PI / 4.f));
            g[e] = c0 + inv * gv;
        }
        w = make_float4(g[0], g[1], g[2], g[3]);
    }

    size_t base; int stride;
    if (s < 2) {                           // low: contiguous rows 40s .. 40s+39
        base   = (size_t)ch * Q_PER_CH + (size_t)(40 * s + r) * 120 + c4;
        stride = 240;
    } else {                               // high class k: rows 80+k+3m
        base   = (size_t)ch * Q_PER_CH + (size_t)(80 + (s - 2) + 3 * r) * 120 + c4;
        stride = 720;
    }

    float acc0 = 0.f, acc1 = 0.f;
    if (act) {
        const float4* p = x + base;
        #pragma unroll 5
        for (int i = 0; i < 20; i++) {
            float4 v = __ldcs(p);
            p += stride;
            acc0 += v.x * w.x + v.y * w.y;
            acc1 += v.z * w.z + v.w * w.w;
        }
    }
    float acc = acc0 + acc1;

    __shared__ float wsum[8];
    __shared__ bool amLast;
    #pragma unroll
    for (int o = 16; o; o >>= 1) acc += __shfl_xor_sync(0xffffffffu, acc, o);
    if ((t & 31) == 0) wsum[t >> 5] = acc;
    __syncthreads();
    if (t < 8) {
        float v = wsum[t];
        #pragma unroll
        for (int o = 4; o; o >>= 1) v += __shfl_xor_sync(0xffu, v, o);
        if (t == 0) d_part[blk] = v;
    }

    // ---- election of the last block -----------------------------------------
    if (t == 0) {
        __threadfence();
        unsigned int old = atomicAdd(&d_count, 1u);
        amLast = (old == (unsigned)(N_BLOCKS - 1));
        if (amLast) d_count = 0;           // reset for next graph replay
    }
    __syncthreads();
    if (!amLast) return;

    // ---- fused MLP (one block, 256 threads) ---------------------------------
    __threadfence();                        // acquire d_part writes
    __shared__ float sg[1024];
    __shared__ float st1[256];

    for (int i = t; i < 1024; i += 256) {
        const float* p = &d_part[i * BLKS_PER_CH];
        sg[i] = ((p[0] + p[1]) + (p[2] + p[3])) + p[4];
    }
    __syncthreads();

    // Stage 1: t1[b][j] = sum_c gap[b][c] * w1[j][c]   (w1 via L1, 16 KB)
    {
        int b = t >> 5, j = t & 31;
        float sacc = 0.f;
        #pragma unroll 8
        for (int c = 0; c < 128; c++) sacc += sg[b * 128 + c] * __ldg(&w1[j * 128 + c]);
        st1[t] = sacc;
    }
    __syncthreads();

    // Stage 2: att[b][c] = sigmoid(sum_j t1[b][j] * w2[c][j])
    for (int i = t; i < 1024; i += 256) {
        int bb = i >> 7, cc = i & 127;
        float z = 0.f;
        #pragma unroll
        for (int jj = 0; jj < 32; jj++) z += st1[bb * 32 + jj] * __ldg(&w2[cc * 32 + jj]);
        d_att[i] = 1.f / (1.f + expf(-z));
    }
}

// ---- Kernel 2: elementwise scale (R4-proven streaming form) ------------------
__global__ __launch_bounds__(256) void scale_kernel(const float4* __restrict__ x,
                                                    float4* __restrict__ out) {
    int q  = blockIdx.x * 256 + threadIdx.x;
    int ch = blockIdx.y;
    if (q < Q_PER_CH) {
        float a = d_att[ch];
        size_t idx = (size_t)ch * Q_PER_CH + q;
        float4 v = __ldcs(&x[idx]);
        v.x *= a; v.y *= a; v.z *= a; v.w *= a;
        __stcs(&out[idx], v);
    }
}

// ---- Launch ------------------------------------------------------------------
extern "C" void kernel_launch(void* const* d_in, const int* in_sizes, int n_in,
                              void* d_out, int out_size) {
    const float* x  = (const float*)d_in[0];
    const float* w1 = (const float*)d_in[1];
    const float* w2 = (const float*)d_in[2];
    float* out = (float*)d_out;

    reduce_kernel<<<N_BLOCKS, 256>>>(reinterpret_cast<const float4*>(x), w1, w2);
    scale_kernel<<<dim3((Q_PER_CH + 255) / 256, N_CH), 256>>>(
        reinterpret_cast<const float4*>(x), reinterpret_cast<float4*>(out));
}

// round 7
// speedup vs baseline: 1.1542x; 1.1542x over previous
#include <cuda_runtime.h>
#include <math.h>

// ---------------------------------------------------------------------------
// BalancedFrequencyAttention, collapsed form (see R2 derivation):
//   gap[b,c] = sum_{h,n} x[b,c,h,n] * w(h,n)
//   w(h,n)   = c0 + [h>=80] * (0.4/48000) * g_{(h-80)%3}(n),  period-12 in n
//   att      = sigmoid(gap @ w1^T @ w2^T);  out = x * att[:,:,None,None]
//
// R7 = best measured pieces reassembled:
//   - reduce: R5 form (5 blocks/ch, constant-register weights) — 61.1 us
//   - mlp:    separate tiny kernel (R5 form) — ~3 us
//   - scale:  1 float4/thread streaming (R6-measured 117.1 us)
// ---------------------------------------------------------------------------

#define N_CH        1024      // B*C
#define Q_PER_CH    24000     // 200*480/4 float4 per channel
#define BLKS_PER_CH 5

__device__ float d_part[N_CH * BLKS_PER_CH];
__device__ float d_att[N_CH];

// ---- Kernel 1: weighted reduction, constant-register weights -----------------
__global__ __launch_bounds__(256, 8) void reduce_kernel(const float4* __restrict__ x) {
    const float c0  = 8.838834764831843e-06f;   // 0.6/sqrt(2)/48000
    const float inv = 8.333333333333334e-06f;   // 0.4/48000
    const float PI  = 3.14159265358979323846f;

    const int blk = blockIdx.x;
    const int ch  = blk / BLKS_PER_CH;
    const int s   = blk - ch * BLKS_PER_CH;

    const int t    = threadIdx.x;
    const int c4   = t & 127;          // float4 column (0..119 active)
    const int r    = t >> 7;           // row-within-pair (0/1)
    const bool act = (c4 < 120);

    // Per-thread constant weight (computed once).
    float4 w = make_float4(c0, c0, c0, c0);
    if (s >= 2) {
        const int k  = s - 2;
        const int n0 = c4 << 2;
        float g[4];
        #pragma unroll
        for (int e = 0; e < 4; e++) {
            float a = (float)(2 * ((n0 + e) % 12) + 1);
            float gv;
            if (k == 0)      gv = cosf(a * (PI / 12.f)) + cosf(a * (PI / 3.f));
            else if (k == 1) gv = cosf(a * (PI / 6.f))  + cosf(a * (5.f * PI / 12.f));
            else             gv = cosf(a * (PI / 4.f));
            g[e] = c0 + inv * gv;
        }
        w = make_float4(g[0], g[1], g[2], g[3]);
    }

    size_t base; int stride;
    if (s < 2) {                           // low: contiguous rows 40s .. 40s+39
        base   = (size_t)ch * Q_PER_CH + (size_t)(40 * s + r) * 120 + c4;
        stride = 240;                      // 2 rows
    } else {                               // high class k: rows 80+k+3m
        base   = (size_t)ch * Q_PER_CH + (size_t)(80 + (s - 2) + 3 * r) * 120 + c4;
        stride = 720;                      // 2 strided rows (6 physical rows)
    }

    float acc0 = 0.f, acc1 = 0.f;
    if (act) {
        const float4* p = x + base;
        #pragma unroll 5
        for (int i = 0; i < 20; i++) {
            float4 v = __ldcs(p);
            p += stride;
            acc0 += v.x * w.x + v.y * w.y;
            acc1 += v.z * w.z + v.w * w.w;
        }
    }
    float acc = acc0 + acc1;

    __shared__ float wsum[8];
    #pragma unroll
    for (int o = 16; o; o >>= 1) acc += __shfl_xor_sync(0xffffffffu, acc, o);
    if ((t & 31) == 0) wsum[t >> 5] = acc;
    __syncthreads();
    if (t < 8) {
        float v = wsum[t];
        #pragma unroll
        for (int o = 4; o; o >>= 1) v += __shfl_xor_sync(0xffu, v, o);
        if (t == 0) d_part[blk] = v;
    }
}

// ---- Kernel 2: fold partials + tiny MLP + sigmoid ----------------------------
__global__ __launch_bounds__(256) void mlp_kernel(const float* __restrict__ w1,
                                                  const float* __restrict__ w2) {
    __shared__ float sg[1024];
    __shared__ float sw1[32][129];   // padded: conflict-free column reads
    __shared__ float sw2[128][33];
    __shared__ float st1[256];
    int tid = threadIdx.x;

    for (int i = tid; i < 1024; i += 256) {
        const float* p = &d_part[i * BLKS_PER_CH];
        sg[i] = ((p[0] + p[1]) + (p[2] + p[3])) + p[4];
    }
    for (int i = tid; i < 4096; i += 256) {
        sw1[i >> 7][i & 127] = w1[i];   // w1[j][c], j<32, c<128
        sw2[i >> 5][i & 31]  = w2[i];   // w2[c][j], c<128, j<32
    }
    __syncthreads();

    // Stage 1: t1[b][j] = sum_c gap[b][c] * w1[j][c]
    int b = tid >> 5, j = tid & 31;
    float sacc = 0.f;
    #pragma unroll 8
    for (int c = 0; c < 128; c++) sacc += sg[b * 128 + c] * sw1[j][c];
    st1[tid] = sacc;
    __syncthreads();

    // Stage 2: att[b][c] = sigmoid(sum_j t1[b][j] * w2[c][j])
    for (int i = tid; i < 1024; i += 256) {
        int bb = i >> 7, cc = i & 127;
        float z = 0.f;
        #pragma unroll
        for (int jj = 0; jj < 32; jj++) z += st1[bb * 32 + jj] * sw2[cc][jj];
        d_att[i] = 1.f / (1.f + expf(-z));
    }
}

// ---- Kernel 3: elementwise scale (streaming, 1 float4/thread) ----------------
__global__ __launch_bounds__(256) void scale_kernel(const float4* __restrict__ x,
                                                    float4* __restrict__ out) {
    int q  = blockIdx.x * 256 + threadIdx.x;
    int ch = blockIdx.y;
    if (q < Q_PER_CH) {
        float a = d_att[ch];
        size_t idx = (size_t)ch * Q_PER_CH + q;
        float4 v = __ldcs(&x[idx]);
        v.x *= a; v.y *= a; v.z *= a; v.w *= a;
        __stcs(&out[idx], v);
    }
}

// ---- Launch ------------------------------------------------------------------
extern "C" void kernel_launch(void* const* d_in, const int* in_sizes, int n_in,
                              void* d_out, int out_size) {
    const float* x  = (const float*)d_in[0];
    const float* w1 = (const float*)d_in[1];
    const float* w2 = (const float*)d_in[2];
    float* out = (float*)d_out;

    reduce_kernel<<<N_CH * BLKS_PER_CH, 256>>>(reinterpret_cast<const float4*>(x));
    mlp_kernel<<<1, 256>>>(w1, w2);
    scale_kernel<<<dim3((Q_PER_CH + 255) / 256, N_CH), 256>>>(
        reinterpret_cast<const float4*>(x), reinterpret_cast<float4*>(out));
}

// round 9
// speedup vs baseline: 1.1709x; 1.0145x over previous
#include <cuda_runtime.h>
#include <math.h>

// ---------------------------------------------------------------------------
// BalancedFrequencyAttention, collapsed form (see R2 derivation):
//   gap[b,c] = sum_{h,n} x[b,c,h,n] * w(h,n)
//   w(h,n)   = c0 + [h>=80] * (0.4/48000) * g_{(h-80)%3}(n),  period-12 in n
//   att      = sigmoid(gap @ w1^T @ w2^T);  out = x * att[:,:,None,None]
//
// R8: same three kernels (each individually at roofline), now chained with
// PDL (programmatic dependent launch):
//   - mlp preloads w1/w2 smem tiles BEFORE cudaGridDependencySynchronize()
//   - scale issues its x LDG BEFORE the sync; only the d_att read waits
//   - scale uses an exact flat grid (96000 x 256, no tail predicate)
// ---------------------------------------------------------------------------

#define N_CH        1024      // B*C
#define Q_PER_CH    24000     // 200*480/4 float4 per channel
#define BLKS_PER_CH 5
#define TOTAL_Q4    (N_CH * Q_PER_CH)        // 24,576,000 (divisible by 256)

__device__ float d_part[N_CH * BLKS_PER_CH];
__device__ float d_att[N_CH];

// ---- Kernel 1: weighted reduction, constant-register weights -----------------
__global__ __launch_bounds__(256, 8) void reduce_kernel(const float4* __restrict__ x) {
    const float c0  = 8.838834764831843e-06f;   // 0.6/sqrt(2)/48000
    const float inv = 8.333333333333334e-06f;   // 0.4/48000
    const float PI  = 3.14159265358979323846f;

    const int blk = blockIdx.x;
    const int ch  = blk / BLKS_PER_CH;
    const int s   = blk - ch * BLKS_PER_CH;

    const int t    = threadIdx.x;
    const int c4   = t & 127;          // float4 column (0..119 active)
    const int r    = t >> 7;           // row-within-pair (0/1)
    const bool act = (c4 < 120);

    // Per-thread constant weight (computed once).
    float4 w = make_float4(c0, c0, c0, c0);
    if (s >= 2) {
        const int k  = s - 2;
        const int n0 = c4 << 2;
        float g[4];
        #pragma unroll
        for (int e = 0; e < 4; e++) {
            float a = (float)(2 * ((n0 + e) % 12) + 1);
            float gv;
            if (k == 0)      gv = cosf(a * (PI / 12.f)) + cosf(a * (PI / 3.f));
            else if (k == 1) gv = cosf(a * (PI / 6.f))  + cosf(a * (5.f * PI / 12.f));
            else             gv = cosf(a * (PI / 4.f));
            g[e] = c0 + inv * gv;
        }
        w = make_float4(g[0], g[1], g[2], g[3]);
    }

    size_t base; int stride;
    if (s < 2) {                           // low: contiguous rows 40s .. 40s+39
        base   = (size_t)ch * Q_PER_CH + (size_t)(40 * s + r) * 120 + c4;
        stride = 240;                      // 2 rows
    } else {                               // high class k: rows 80+k+3m
        base   = (size_t)ch * Q_PER_CH + (size_t)(80 + (s - 2) + 3 * r) * 120 + c4;
        stride = 720;                      // 2 strided rows (6 physical rows)
    }

    float acc0 = 0.f, acc1 = 0.f;
    if (act) {
        const float4* p = x + base;
        #pragma unroll 5
        for (int i = 0; i < 20; i++) {
            float4 v = __ldcs(p);
            p += stride;
            acc0 += v.x * w.x + v.y * w.y;
            acc1 += v.z * w.z + v.w * w.w;
        }
    }
    float acc = acc0 + acc1;

    __shared__ float wsum[8];
    #pragma unroll
    for (int o = 16; o; o >>= 1) acc += __shfl_xor_sync(0xffffffffu, acc, o);
    if ((t & 31) == 0) wsum[t >> 5] = acc;
    __syncthreads();
    if (t < 8) {
        float v = wsum[t];
        #pragma unroll
        for (int o = 4; o; o >>= 1) v += __shfl_xor_sync(0xffu, v, o);
        if (t == 0) d_part[blk] = v;
    }
}

// ---- Kernel 2: fold partials + tiny MLP + sigmoid (PDL consumer) -------------
__global__ __launch_bounds__(256) void mlp_kernel(const float* __restrict__ w1,
                                                  const float* __restrict__ w2) {
    __shared__ float sg[1024];
    __shared__ float sw1[32][129];   // padded: conflict-free column reads
    __shared__ float sw2[128][33];
    __shared__ float st1[256];
    int tid = threadIdx.x;

    // Independent of d_part: overlap with reduce_kernel tail.
    for (int i = tid; i < 4096; i += 256) {
        sw1[i >> 7][i & 127] = w1[i];   // w1[j][c], j<32, c<128
        sw2[i >> 5][i & 31]  = w2[i];   // w2[c][j], c<128, j<32
    }

    cudaGridDependencySynchronize();    // wait for reduce_kernel's d_part

    for (int i = tid; i < 1024; i += 256) {
        const float* p = &d_part[i * BLKS_PER_CH];
        sg[i] = ((p[0] + p[1]) + (p[2] + p[3])) + p[4];
    }
    __syncthreads();

    // Stage 1: t1[b][j] = sum_c gap[b][c] * w1[j][c]
    int b = tid >> 5, j = tid & 31;
    float sacc = 0.f;
    #pragma unroll 8
    for (int c = 0; c < 128; c++) sacc += sg[b * 128 + c] * sw1[j][c];
    st1[tid] = sacc;
    __syncthreads();

    // Stage 2: att[b][c] = sigmoid(sum_j t1[b][j] * w2[c][j])
    for (int i = tid; i < 1024; i += 256) {
        int bb = i >> 7, cc = i & 127;
        float z = 0.f;
        #pragma unroll
        for (int jj = 0; jj < 32; jj++) z += st1[bb * 32 + jj] * sw2[cc][jj];
        d_att[i] = 1.f / (1.f + expf(-z));
    }
}

// ---- Kernel 3: elementwise scale, exact flat grid (PDL consumer) -------------
__global__ __launch_bounds__(256) void scale_kernel(const float4* __restrict__ x,
                                                    float4* __restrict__ out) {
    unsigned idx = blockIdx.x * 256u + threadIdx.x;   // < 24,576,000
    float4 v = __ldcs(&x[idx]);          // independent of mlp: issue before sync
    unsigned ch = idx / (unsigned)Q_PER_CH;           // mul-hi, one per thread

    cudaGridDependencySynchronize();     // wait only for d_att

    float a = d_att[ch];
    v.x *= a; v.y *= a; v.z *= a; v.w *= a;
    __stcs(&out[idx], v);
}

// ---- Launch ------------------------------------------------------------------
extern "C" void kernel_launch(void* const* d_in, const int* in_sizes, int n_in,
                              void* d_out, int out_size) {
    const float* x  = (const float*)d_in[0];
    const float* w1 = (const float*)d_in[1];
    const float* w2 = (const float*)d_in[2];
    float* out = (float*)d_out;

    reduce_kernel<<<N_CH * BLKS_PER_CH, 256>>>(reinterpret_cast<const float4*>(x));

    cudaLaunchAttribute attr[1];
    attr[0].id = cudaLaunchAttributeProgrammaticStreamSerialization;
    attr[0].val.programmaticStreamSerializationAllowed = 1;

    {   // mlp: PDL-overlapped with reduce tail
        cudaLaunchConfig_t cfg = {};
        cfg.gridDim = dim3(1, 1, 1);
        cfg.blockDim = dim3(256, 1, 1);
        cfg.dynamicSmemBytes = 0;
        cfg.stream = 0;
        cfg.attrs = attr;
        cfg.numAttrs = 1;
        cudaLaunchKernelEx(&cfg, mlp_kernel, w1, w2);
    }
    {   // scale: PDL-overlapped with mlp
        cudaLaunchConfig_t cfg = {};
        cfg.gridDim = dim3(TOTAL_Q4 / 256, 1, 1);     // 96000 blocks, no tail
        cfg.blockDim = dim3(256, 1, 1);
        cfg.dynamicSmemBytes = 0;
        cfg.stream = 0;
        cfg.attrs = attr;
        cfg.numAttrs = 1;
        cudaLaunchKernelEx(&cfg, scale_kernel,
                           reinterpret_cast<const float4*>(x),
                           reinterpret_cast<float4*>(out));
    }
}

// round 10
// speedup vs baseline: 1.1751x; 1.0036x over previous
#include <cuda_runtime.h>
#include <math.h>

// ---------------------------------------------------------------------------
// BalancedFrequencyAttention, collapsed form (see R2 derivation):
//   gap[b,c] = sum_{h,n} x[b,c,h,n] * w(h,n)
//   w(h,n)   = c0 + [h>=80] * (0.4/48000) * g_{(h-80)%3}(n),  period-12 in n
//   att      = sigmoid(gap @ w1^T @ w2^T);  out = x * att[:,:,None,None]
//
// R9: PDL chain with EARLY programmatic triggers (release dependents at
// last-block-store, not grid teardown); scale = 2 float4/thread on an exact
// flat grid (48000 x 512, zero predicates), both loads issued pre-sync.
// Reduce kernel untouched (measured at roofline: 60.1 us, 6.6 TB/s).
// ---------------------------------------------------------------------------

#define N_CH        1024      // B*C
#define Q_PER_CH    24000     // 200*480/4 float4 per channel
#define BLKS_PER_CH 5
#define TOTAL_Q4    (N_CH * Q_PER_CH)        // 24,576,000 = 48000 * 512

__device__ float d_part[N_CH * BLKS_PER_CH];
__device__ float d_att[N_CH];

// ---- Kernel 1: weighted reduction, constant-register weights -----------------
__global__ __launch_bounds__(256, 8) void reduce_kernel(const float4* __restrict__ x) {
    const float c0  = 8.838834764831843e-06f;   // 0.6/sqrt(2)/48000
    const float inv = 8.333333333333334e-06f;   // 0.4/48000
    const float PI  = 3.14159265358979323846f;

    const int blk = blockIdx.x;
    const int ch  = blk / BLKS_PER_CH;
    const int s   = blk - ch * BLKS_PER_CH;

    const int t    = threadIdx.x;
    const int c4   = t & 127;          // float4 column (0..119 active)
    const int r    = t >> 7;           // row-within-pair (0/1)
    const bool act = (c4 < 120);

    // Per-thread constant weight (computed once).
    float4 w = make_float4(c0, c0, c0, c0);
    if (s >= 2) {
        const int k  = s - 2;
        const int n0 = c4 << 2;
        float g[4];
        #pragma unroll
        for (int e = 0; e < 4; e++) {
            float a = (float)(2 * ((n0 + e) % 12) + 1);
            float gv;
            if (k == 0)      gv = cosf(a * (PI / 12.f)) + cosf(a * (PI / 3.f));
            else if (k == 1) gv = cosf(a * (PI / 6.f))  + cosf(a * (5.f * PI / 12.f));
            else             gv = cosf(a * (PI / 4.f));
            g[e] = c0 + inv * gv;
        }
        w = make_float4(g[0], g[1], g[2], g[3]);
    }

    size_t base; int stride;
    if (s < 2) {                           // low: contiguous rows 40s .. 40s+39
        base   = (size_t)ch * Q_PER_CH + (size_t)(40 * s + r) * 120 + c4;
        stride = 240;                      // 2 rows
    } else {                               // high class k: rows 80+k+3m
        base   = (size_t)ch * Q_PER_CH + (size_t)(80 + (s - 2) + 3 * r) * 120 + c4;
        stride = 720;                      // 2 strided rows (6 physical rows)
    }

    float acc0 = 0.f, acc1 = 0.f;
    if (act) {
        const float4* p = x + base;
        #pragma unroll 5
        for (int i = 0; i < 20; i++) {
            float4 v = __ldcs(p);
            p += stride;
            acc0 += v.x * w.x + v.y * w.y;
            acc1 += v.z * w.z + v.w * w.w;
        }
    }
    float acc = acc0 + acc1;

    __shared__ float wsum[8];
    #pragma unroll
    for (int o = 16; o; o >>= 1) acc += __shfl_xor_sync(0xffffffffu, acc, o);
    if ((t & 31) == 0) wsum[t >> 5] = acc;
    __syncthreads();
    if (t < 8) {
        float v = wsum[t];
        #pragma unroll
        for (int o = 4; o; o >>= 1) v += __shfl_xor_sync(0xffu, v, o);
        if (t == 0) { d_part[blk] = v; __threadfence(); }
    }
    __syncthreads();
    cudaTriggerProgrammaticLaunchCompletion();   // release mlp at last store
}

// ---- Kernel 2: fold partials + tiny MLP + sigmoid (PDL) ----------------------
__global__ __launch_bounds__(256) void mlp_kernel(const float* __restrict__ w1,
                                                  const float* __restrict__ w2) {
    __shared__ float sg[1024];
    __shared__ float sw1[32][129];   // padded: conflict-free column reads
    __shared__ float sw2[128][33];
    __shared__ float st1[256];
    int tid = threadIdx.x;

    // Independent of d_part: overlaps reduce_kernel execution.
    for (int i = tid; i < 4096; i += 256) {
        sw1[i >> 7][i & 127] = w1[i];   // w1[j][c], j<32, c<128
        sw2[i >> 5][i & 31]  = w2[i];   // w2[c][j], c<128, j<32
    }

    cudaGridDependencySynchronize();    // wait for reduce_kernel's d_part

    for (int i = tid; i < 1024; i += 256) {
        const float* p = &d_part[i * BLKS_PER_CH];
        sg[i] = ((p[0] + p[1]) + (p[2] + p[3])) + p[4];
    }
    __syncthreads();

    // Stage 1: t1[b][j] = sum_c gap[b][c] * w1[j][c]
    int b = tid >> 5, j = tid & 31;
    float sacc = 0.f;
    #pragma unroll 8
    for (int c = 0; c < 128; c++) sacc += sg[b * 128 + c] * sw1[j][c];
    st1[tid] = sacc;
    __syncthreads();

    // Stage 2: att[b][c] = sigmoid(sum_j t1[b][j] * w2[c][j])
    for (int i = tid; i < 1024; i += 256) {
        int bb = i >> 7, cc = i & 127;
        float z = 0.f;
        #pragma unroll
        for (int jj = 0; jj < 32; jj++) z += st1[bb * 32 + jj] * sw2[cc][jj];
        d_att[i] = 1.f / (1.f + expf(-z));
    }
    __threadfence();
    __syncthreads();
    cudaTriggerProgrammaticLaunchCompletion();   // release scale at d_att store
}

// ---- Kernel 3: scale, 2 float4/thread, exact flat grid (PDL) -----------------
__global__ __launch_bounds__(256) void scale_kernel(const float4* __restrict__ x,
                                                    float4* __restrict__ out) {
    unsigned i0 = blockIdx.x * 512u + threadIdx.x;    // < 24,576,000 always
    unsigned i1 = i0 + 256u;
    float4 v0 = __ldcs(&x[i0]);          // both loads issue before the sync
    float4 v1 = __ldcs(&x[i1]);
    unsigned c0 = i0 / (unsigned)Q_PER_CH;
    unsigned c1 = i1 / (unsigned)Q_PER_CH;

    cudaGridDependencySynchronize();     // wait only for d_att

    float a0 = d_att[c0];
    float a1 = d_att[c1];
    v0.x *= a0; v0.y *= a0; v0.z *= a0; v0.w *= a0;
    v1.x *= a1; v1.y *= a1; v1.z *= a1; v1.w *= a1;
    __stcs(&out[i0], v0);
    __stcs(&out[i1], v1);
}

// ---- Launch ------------------------------------------------------------------
extern "C" void kernel_launch(void* const* d_in, const int* in_sizes, int n_in,
                              void* d_out, int out_size) {
    const float* x  = (const float*)d_in[0];
    const float* w1 = (const float*)d_in[1];
    const float* w2 = (const float*)d_in[2];
    float* out = (float*)d_out;

    reduce_kernel<<<N_CH * BLKS_PER_CH, 256>>>(reinterpret_cast<const float4*>(x));

    cudaLaunchAttribute attr[1];
    attr[0].id = cudaLaunchAttributeProgrammaticStreamSerialization;
    attr[0].val.programmaticStreamSerializationAllowed = 1;

    {   // mlp: PDL-overlapped with reduce
        cudaLaunchConfig_t cfg = {};
        cfg.gridDim = dim3(1, 1, 1);
        cfg.blockDim = dim3(256, 1, 1);
        cfg.dynamicSmemBytes = 0;
        cfg.stream = 0;
        cfg.attrs = attr;
        cfg.numAttrs = 1;
        cudaLaunchKernelEx(&cfg, mlp_kernel, w1, w2);
    }
    {   // scale: PDL-overlapped with mlp
        cudaLaunchConfig_t cfg = {};
        cfg.gridDim = dim3(TOTAL_Q4 / 512, 1, 1);     // 48000 blocks, no tail
        cfg.blockDim = dim3(256, 1, 1);
        cfg.dynamicSmemBytes = 0;
        cfg.stream = 0;
        cfg.attrs = attr;
        cfg.numAttrs = 1;
        cudaLaunchKernelEx(&cfg, scale_kernel,
                           reinterpret_cast<const float4*>(x),
                           reinterpret_cast<float4*>(out));
    }
}